// round 12
// baseline (speedup 1.0000x reference)
#include <cuda_runtime.h>
#include <cuda_bf16.h>
#include <cuda_fp16.h>
#include <math.h>

// Problem constants
#define NN 50000
#define EE 1600000
#define GG 512
#define INF_ 128
#define HID 128
#define PROJ 256
#define N2 (2 * NN)
#define E2 (2 * EE)
#define NPART 256   // >= ceil(N2/512) = 196

// ---------------- merged device scratch (both encoders) ----------------
// All vector-cast arrays have 16B-multiple sizes; odd-sized off[] goes last.
struct alignas(16) MergedScratch {
    __half Ph[N2 * HID];      // fp16 (pre)scaled features for gather
    float Ha[N2 * HID];
    float Hb[N2 * HID];
    float pool[2 * GG * HID];
    float t [2 * GG * PROJ];
    float t2[2 * GG * PROJ];
    float q [2 * GG * (PROJ/2)];
    float dinv[N2];
    int   cnt[N2];
    int   csr[E2];
    int   part[NPART];
    int   off[N2 + 1];        // odd size -> keep last
};
__device__ MergedScratch g_s;

// ---------------- CSR build (merged: encoder-2 node ids offset by n) --------
__global__ void k_zero(int* cnt, int n2) {
    int i = blockIdx.x * blockDim.x + threadIdx.x;
    if (i < n2) cnt[i] = 0;
}

__global__ void k_degree2(const int* __restrict__ dst1, const int* __restrict__ dst2,
                          int* cnt, int e, int n) {
    int i = blockIdx.x * blockDim.x + threadIdx.x;
    if (i < 2 * e) {
        int d = (i < e) ? dst1[i] : (dst2[i - e] + n);
        atomicAdd(&cnt[d], 1);
    }
}

__global__ void k_part(const int* __restrict__ cnt, int* part, int n2) {
    __shared__ int red[16];
    int i = blockIdx.x * blockDim.x + threadIdx.x;
    int v = (i < n2) ? cnt[i] : 0;
    int lane = threadIdx.x & 31, wid = threadIdx.x >> 5;
    #pragma unroll
    for (int o = 16; o; o >>= 1) v += __shfl_down_sync(0xffffffffu, v, o);
    if (lane == 0) red[wid] = v;
    __syncthreads();
    if (wid == 0) {
        int s = (lane < (blockDim.x >> 5)) ? red[lane] : 0;
        #pragma unroll
        for (int o = 16; o; o >>= 1) s += __shfl_down_sync(0xffffffffu, s, o);
        if (lane == 0) part[blockIdx.x] = s;
    }
}

__global__ void k_scanpart(int* part, int nb) {
    __shared__ int sh[NPART];
    int tid = threadIdx.x;
    sh[tid] = (tid < nb) ? part[tid] : 0;
    __syncthreads();
    for (int d = 1; d < NPART; d <<= 1) {
        int v = (tid >= d) ? sh[tid - d] : 0;
        __syncthreads();
        sh[tid] += v;
        __syncthreads();
    }
    if (tid < nb) part[tid] = (tid == 0) ? 0 : sh[tid - 1];
}

__global__ void k_off(int* cnt, const int* __restrict__ part, int* off,
                      float* dinv, int n2) {
    __shared__ int wsum[16];
    int i = blockIdx.x * blockDim.x + threadIdx.x;
    int lane = threadIdx.x & 31, wid = threadIdx.x >> 5;
    int nw = blockDim.x >> 5;
    int v = (i < n2) ? cnt[i] : 0;
    int x = v;
    #pragma unroll
    for (int d = 1; d < 32; d <<= 1) {
        int y = __shfl_up_sync(0xffffffffu, x, d);
        if (lane >= d) x += y;
    }
    if (lane == 31) wsum[wid] = x;
    __syncthreads();
    if (wid == 0) {
        int s = (lane < nw) ? wsum[lane] : 0;
        #pragma unroll
        for (int d = 1; d < 32; d <<= 1) {
            int y = __shfl_up_sync(0xffffffffu, s, d);
            if (lane >= d) s += y;
        }
        wsum[lane] = s;
    }
    __syncthreads();
    int excl = x - v + ((wid == 0) ? 0 : wsum[wid - 1]) + part[blockIdx.x];
    if (i < n2) {
        off[i]  = excl;
        dinv[i] = rsqrtf((float)(v + 1));
        cnt[i]  = excl;          // cursor for fill
        if (i == n2 - 1) off[n2] = excl + v;
    }
}

__global__ void k_fill2(const int* __restrict__ src1, const int* __restrict__ dst1,
                        const int* __restrict__ src2, const int* __restrict__ dst2,
                        int* cnt, int* csr, int e, int n) {
    int i = blockIdx.x * blockDim.x + threadIdx.x;
    if (i < 2 * e) {
        int s, d;
        if (i < e) { s = src1[i];     d = dst1[i]; }
        else       { s = src2[i - e] + n; d = dst2[i - e] + n; }
        int pos = atomicAdd(&cnt[d], 1);
        csr[pos] = s;
    }
}

// ---------------- packed-f32x2 GEMM, optional dinv prescale, fp16 out -------
__device__ __forceinline__ void fma_f32x2(unsigned long long& d,
                                          unsigned long long a,
                                          unsigned long long b) {
    asm("fma.rn.f32x2 %0, %1, %2, %0;" : "+l"(d) : "l"(a), "l"(b));
}

__global__ __launch_bounds__(256) void k_gemm_p2(
        const float* __restrict__ A, const float* __restrict__ W,
        const float* __restrict__ dinv, __half* __restrict__ out, int M) {
    extern __shared__ float sm[];
    float2* Ws2 = (float2*)sm;            // [64][128] float2 = 64KB
    float*  As  = sm + 64 * 128 * 2;      // [64][128] float  = 32KB
    int tid = threadIdx.x;

    for (int i = tid; i < 64 * 32; i += 256) {
        int kp = i >> 5, c4 = i & 31;
        float4 w0 = ((const float4*)W)[(2 * kp)     * 32 + c4];
        float4 w1 = ((const float4*)W)[(2 * kp + 1) * 32 + c4];
        float2* dstp = Ws2 + kp * 128 + (c4 << 2);
        dstp[0] = make_float2(w0.x, w1.x);
        dstp[1] = make_float2(w0.y, w1.y);
        dstp[2] = make_float2(w0.z, w1.z);
        dstp[3] = make_float2(w0.w, w1.w);
    }
    int rowbase = blockIdx.x * 64;
    for (int i = tid; i < 64 * 32; i += 256) {
        int r = i >> 5, c4 = i & 31;
        float4 v = make_float4(0.f, 0.f, 0.f, 0.f);
        if (rowbase + r < M) v = ((const float4*)A)[(rowbase + r) * 32 + c4];
        *(float4*)(As + r * 128 + (c4 << 2)) = v;
    }
    __syncthreads();

    int lane = tid & 31, w = tid >> 5;
    unsigned long long acc[8][4];
    #pragma unroll
    for (int r = 0; r < 8; r++)
        #pragma unroll
        for (int j = 0; j < 4; j++) acc[r][j] = 0ull;

    const unsigned long long* Wsu = (const unsigned long long*)Ws2;
    #pragma unroll 4
    for (int kp = 0; kp < 64; kp++) {
        unsigned long long w2[4];
        #pragma unroll
        for (int j = 0; j < 4; j++) w2[j] = Wsu[kp * 128 + lane + 32 * j];
        #pragma unroll
        for (int r = 0; r < 8; r++) {
            unsigned long long a2 =
                *(const unsigned long long*)(As + (w + r * 8) * 128 + 2 * kp);
            #pragma unroll
            for (int j = 0; j < 4; j++) fma_f32x2(acc[r][j], a2, w2[j]);
        }
    }

    #pragma unroll
    for (int r = 0; r < 8; r++) {
        int row = rowbase + w + r * 8;
        if (row < M) {
            float dv = dinv ? dinv[row] : 1.f;
            #pragma unroll
            for (int j = 0; j < 4; j++) {
                unsigned long long u = acc[r][j];
                float lo = __uint_as_float((unsigned int)(u & 0xffffffffu));
                float hi = __uint_as_float((unsigned int)(u >> 32));
                out[row * 128 + lane + 32 * j] = __float2half_rn(dv * (lo + hi));
            }
        }
    }
}
#define GEMM_SMEM ((64 * 128 * 2 + 64 * 128) * sizeof(float))

// ---------------- prescale (layer 1 only): Ph[row] *= dinv[row] -------------
__global__ void k_prescale(uint2* Ph, const float* __restrict__ dinv, int n2) {
    int i = blockIdx.x * blockDim.x + threadIdx.x;
    if (i >= n2 * 32) return;
    int row = i >> 5;
    float dv = dinv[row];
    uint2 u = Ph[i];
    __half2* h = (__half2*)&u;
    float2 f0 = __half22float2(h[0]);
    float2 f1 = __half22float2(h[1]);
    h[0] = __floats2half2_rn(dv * f0.x, dv * f0.y);
    h[1] = __floats2half2_rn(dv * f1.x, dv * f1.y);
    Ph[i] = u;
}

// ---------------- gather: warp per node, prescaled fp16 features ------------
__global__ void k_gather(const uint2* __restrict__ P, const float* __restrict__ bias,
                         const float4* __restrict__ Hres, float4* __restrict__ out,
                         const int* __restrict__ off, const int* __restrict__ csr,
                         const float* __restrict__ dinv, int n2, int mode) {
    int gw = (blockIdx.x * blockDim.x + threadIdx.x) >> 5;
    if (gw >= n2) return;
    int lane = threadIdx.x & 31;
    int v = gw;
    int off0 = off[v], off1 = off[v + 1];
    float dv = dinv[v];
    uint2 bu = P[v * 32 + lane];
    const __half2* bh = (const __half2*)&bu;
    float2 b0 = __half22float2(bh[0]);
    float2 b1 = __half22float2(bh[1]);
    float4 acc = make_float4(b0.x, b0.y, b1.x, b1.y);   // self term P[v]
    for (int j = off0; j < off1; j += 32) {
        int idx = j + lane;
        int u = (idx < off1) ? csr[idx] : 0;
        int m = off1 - j; if (m > 32) m = 32;
        #pragma unroll 4
        for (int i = 0; i < m; i++) {
            int uu = __shfl_sync(0xffffffffu, u, i);
            uint2 hu = P[uu * 32 + lane];
            const __half2* hh = (const __half2*)&hu;
            float2 f0 = __half22float2(hh[0]);
            float2 f1 = __half22float2(hh[1]);
            acc.x += f0.x; acc.y += f0.y;
            acc.z += f1.x; acc.w += f1.y;
        }
    }
    const float4* b4 = (const float4*)bias;
    float4 bb = b4[lane];
    float4 r;
    r.x = fmaxf(fmaf(dv, acc.x, bb.x), 0.f);
    r.y = fmaxf(fmaf(dv, acc.y, bb.y), 0.f);
    r.z = fmaxf(fmaf(dv, acc.z, bb.z), 0.f);
    r.w = fmaxf(fmaf(dv, acc.w, bb.w), 0.f);
    if (mode == 1) {
        float4 h = Hres[v * 32 + lane];
        r.x += h.x; r.y += h.y; r.z += h.z; r.w += h.w;
    }
    out[v * 32 + lane] = r;
}

// ---------------- pooling (both encoders; binary-search bounds) -------------
__global__ void k_pool2(const float4* __restrict__ H, float4* __restrict__ pool,
                        const int* __restrict__ bt1, const int* __restrict__ bt2,
                        int n, int g) {
    int gw = (blockIdx.x * blockDim.x + threadIdx.x) >> 5;
    if (gw >= 2 * g) return;
    int lane = threadIdx.x & 31;
    int enc = (gw >= g) ? 1 : 0;
    int gid = gw - enc * g;
    const int* batch = enc ? bt2 : bt1;
    int rowbase = enc * n;
    int lo = 0, hi = n;
    while (lo < hi) { int mid = (lo + hi) >> 1; if (batch[mid] < gid) lo = mid + 1; else hi = mid; }
    int s = lo;
    hi = n;
    while (lo < hi) { int mid = (lo + hi) >> 1; if (batch[mid] < gid + 1) lo = mid + 1; else hi = mid; }
    int e = lo;
    float4 acc = make_float4(0.f, 0.f, 0.f, 0.f);
    for (int r = s; r < e; r++) {
        float4 v = H[(rowbase + r) * 32 + lane];
        acc.x += v.x; acc.y += v.y; acc.z += v.z; acc.w += v.w;
    }
    float sc = (e > s) ? 1.0f / (float)(e - s) : 0.f;
    pool[gw * 32 + lane] = make_float4(acc.x * sc, acc.y * sc, acc.z * sc, acc.w * sc);
}

// ---------------- small GEMM: warp per row (batched M=1024) ----------------
template <int NPER>
__global__ void k_gemm_small(const float* __restrict__ A, const float* __restrict__ W,
                             const float* __restrict__ bias, float* __restrict__ out,
                             int M, int K, int N, int relu) {
    int gw = (blockIdx.x * blockDim.x + threadIdx.x) >> 5;
    if (gw >= M) return;
    int lane = threadIdx.x & 31;
    float acc[NPER];
    #pragma unroll
    for (int j = 0; j < NPER; j++) acc[j] = 0.f;
    const float* a = A + gw * K;
    for (int k = 0; k < K; k++) {
        float av = __ldg(a + k);
        const float* wr = W + k * N;
        #pragma unroll
        for (int j = 0; j < NPER; j++) acc[j] += av * __ldg(wr + lane + 32 * j);
    }
    #pragma unroll
    for (int j = 0; j < NPER; j++) {
        float v = acc[j] + bias[lane + 32 * j];
        if (relu) v = fmaxf(v, 0.f);
        out[gw * N + lane + 32 * j] = v;
    }
}

// ---------------- batchnorm: per-encoder stats, grid = 2*cols ---------------
__global__ void k_bn2(const float* __restrict__ x, const float* __restrict__ gamma,
                      const float* __restrict__ beta, float* __restrict__ out,
                      int rows, int cols, int relu) {
    int col = blockIdx.x % cols;
    int enc = blockIdx.x / cols;
    const float* xe = x + (size_t)enc * rows * cols;
    float* oute = out + (size_t)enc * rows * cols;
    int tid = threadIdx.x, lane = tid & 31, wid = tid >> 5;
    __shared__ float red[8];
    __shared__ float s_m, s_inv;
    float s = 0.f, s2 = 0.f;
    for (int r = tid; r < rows; r += blockDim.x) {
        float v = xe[r * cols + col];
        s += v; s2 += v * v;
    }
    #pragma unroll
    for (int o = 16; o; o >>= 1) {
        s  += __shfl_down_sync(0xffffffffu, s, o);
        s2 += __shfl_down_sync(0xffffffffu, s2, o);
    }
    if (lane == 0) { red[wid] = s; red[4 + wid] = s2; }
    __syncthreads();
    if (tid == 0) {
        float ts = red[0] + red[1] + red[2] + red[3];
        float t2 = red[4] + red[5] + red[6] + red[7];
        float m = ts / rows;
        float var = t2 / rows - m * m;
        s_m = m;
        s_inv = rsqrtf(var + 1e-5f);
    }
    __syncthreads();
    float m = s_m, inv = s_inv, ga = gamma[col], be = beta[col];
    for (int r = tid; r < rows; r += blockDim.x) {
        float v = ga * (xe[r * cols + col] - m) * inv + be;
        if (relu) v = fmaxf(v, 0.f);
        oute[r * cols + col] = v;
    }
}

// ---------------- host orchestration ----------------
extern "C" void kernel_launch(void* const* d_in, const int* in_sizes, int n_in,
                              void* d_out, int out_size) {
    const float* x1  = (const float*)d_in[0];
    const int*   ei1 = (const int*)  d_in[1];
    const int*   bt1 = (const int*)  d_in[2];
    const float* x2  = (const float*)d_in[3];
    const int*   ei2 = (const int*)  d_in[4];
    const int*   bt2 = (const int*)  d_in[5];
    const float* W1  = (const float*)d_in[6];
    const float* b1  = (const float*)d_in[7];
    const float* W2  = (const float*)d_in[8];
    const float* b2  = (const float*)d_in[9];
    const float* W3  = (const float*)d_in[10];
    const float* b3  = (const float*)d_in[11];
    const float* Wp1 = (const float*)d_in[12];
    const float* bp1 = (const float*)d_in[13];
    const float* ga1 = (const float*)d_in[14];
    const float* be1 = (const float*)d_in[15];
    const float* Wp2 = (const float*)d_in[16];
    const float* bp2 = (const float*)d_in[17];
    const float* ga2 = (const float*)d_in[18];
    const float* be2 = (const float*)d_in[19];
    const float* Wq1 = (const float*)d_in[20];
    const float* bq1 = (const float*)d_in[21];
    const float* Wq2 = (const float*)d_in[22];
    const float* bq2 = (const float*)d_in[23];

    int n = in_sizes[0] / INF_;
    int e = in_sizes[1] / 2;
    int g = GG;
    int n2 = 2 * n;

    static bool init = false;
    static cudaStream_t sB;
    static cudaEvent_t evFork, evJoin;
    if (!init) {
        cudaStreamCreateWithFlags(&sB, cudaStreamNonBlocking);
        cudaEventCreateWithFlags(&evFork, cudaEventDisableTiming);
        cudaEventCreateWithFlags(&evJoin, cudaEventDisableTiming);
        cudaFuncSetAttribute(k_gemm_p2, cudaFuncAttributeMaxDynamicSharedMemorySize,
                             GEMM_SMEM);
        init = true;
    }

    MergedScratch* S;
    cudaGetSymbolAddress((void**)&S, g_s);

    const int* src1 = ei1; const int* dst1 = ei1 + e;
    const int* src2 = ei2; const int* dst2 = ei2 + e;

    float* out = (float*)d_out;
    float* pout = out;                      // p1|p2 contiguous [2g, PROJ]
    float* zout = out + 2 * (size_t)g * PROJ; // z1|z2 contiguous [2g, PROJ]

    int tb = 256;
    int nb512 = (n2 + 511) / 512;           // 196 <= NPART

    // ---- fork: CSR build on sB, layer-1 GEMMs (no dinv) on stream 0 ----
    cudaEventRecord(evFork, 0);
    cudaStreamWaitEvent(sB, evFork, 0);

    k_zero   <<<(n2 + tb - 1) / tb, tb, 0, sB>>>(S->cnt, n2);
    k_degree2<<<(2 * e + tb - 1) / tb, tb, 0, sB>>>(dst1, dst2, S->cnt, e, n);
    k_part   <<<nb512, 512, 0, sB>>>(S->cnt, S->part, n2);
    k_scanpart<<<1, NPART, 0, sB>>>(S->part, nb512);
    k_off    <<<nb512, 512, 0, sB>>>(S->cnt, S->part, S->off, S->dinv, n2);
    k_fill2  <<<(2 * e + tb - 1) / tb, tb, 0, sB>>>(src1, dst1, src2, dst2,
                                                    S->cnt, S->csr, e, n);

    int gemm_grid1 = (n + 63) / 64;
    k_gemm_p2<<<gemm_grid1, 256, GEMM_SMEM, 0>>>(x1, W1, nullptr, S->Ph, n);
    k_gemm_p2<<<gemm_grid1, 256, GEMM_SMEM, 0>>>(x2, W1, nullptr, S->Ph + (size_t)n * HID, n);

    cudaEventRecord(evJoin, sB);
    cudaStreamWaitEvent(0, evJoin, 0);

    // ---- merged pipeline on stream 0 ----
    int gemm_grid = (n2 + 63) / 64;
    int gath_grid = (n2 * 32 + tb - 1) / tb;
    const uint2* Ph = (const uint2*)S->Ph;
    float4* Ha = (float4*)S->Ha;
    float4* Hb = (float4*)S->Hb;

    k_prescale<<<(n2 * 32 + tb - 1) / tb, tb>>>((uint2*)S->Ph, S->dinv, n2);
    k_gather<<<gath_grid, tb>>>(Ph, b1, nullptr, Ha, S->off, S->csr, S->dinv, n2, 0);
    k_gemm_p2<<<gemm_grid, 256, GEMM_SMEM>>>(S->Ha, W2, S->dinv, S->Ph, n2);
    k_gather<<<gath_grid, tb>>>(Ph, b2, (const float4*)Ha, Hb, S->off, S->csr, S->dinv, n2, 1);
    k_gemm_p2<<<gemm_grid, 256, GEMM_SMEM>>>(S->Hb, W3, S->dinv, S->Ph, n2);
    k_gather<<<gath_grid, tb>>>(Ph, b3, (const float4*)Hb, Ha, S->off, S->csr, S->dinv, n2, 1);

    k_pool2<<<(2 * g * 32 + tb - 1) / tb, tb>>>((const float4*)Ha, (float4*)S->pool,
                                                bt1, bt2, n, g);

    // ---- batched head: M = 2g = 1024, BN per-encoder ----
    int M2 = 2 * g;
    int gw_blocks = (M2 * 32 + 255) / 256;
    k_gemm_small<8><<<gw_blocks, 256>>>(S->pool, Wp1, bp1, S->t, M2, HID, PROJ, 0);
    k_bn2<<<2 * PROJ, 128>>>(S->t, ga1, be1, S->t, g, PROJ, 1);
    k_gemm_small<8><<<gw_blocks, 256>>>(S->t, Wp2, bp2, S->t2, M2, PROJ, PROJ, 0);
    k_bn2<<<2 * PROJ, 128>>>(S->t2, ga2, be2, zout, g, PROJ, 0);
    k_gemm_small<4><<<gw_blocks, 256>>>(zout, Wq1, bq1, S->q, M2, PROJ, PROJ / 2, 1);
    k_gemm_small<8><<<gw_blocks, 256>>>(S->q, Wq2, bq2, pout, M2, PROJ / 2, PROJ, 0);
}

// round 13
// speedup vs baseline: 1.0232x; 1.0232x over previous
#include <cuda_runtime.h>
#include <cuda_bf16.h>
#include <cuda_fp16.h>
#include <math.h>

// Problem constants
#define NN 50000
#define EE 1600000
#define GG 512
#define INF_ 128
#define HID 128
#define PROJ 256
#define N2 (2 * NN)
#define E2 (2 * EE)
#define NPART 256   // >= ceil(N2/512) = 196

// ---------------- merged device scratch (both encoders) ----------------
struct alignas(16) MergedScratch {
    __half Ph[N2 * HID];      // fp16 (pre)scaled features for gather
    float Ha[N2 * HID];
    float Hb[N2 * HID];
    float pool[2 * GG * HID];
    float t [2 * GG * PROJ];
    float t2[2 * GG * PROJ];
    float q [2 * GG * (PROJ/2)];
    float dinv[N2];
    int   cnt[N2];
    int   csr[E2];
    int   part[NPART];
    int   off[N2 + 1];        // odd size -> keep last
};
__device__ MergedScratch g_s;

// ---------------- CSR build (merged: encoder-2 node ids offset by n) --------
__global__ void k_zero(int* cnt, int n2) {
    int i = blockIdx.x * blockDim.x + threadIdx.x;
    if (i < n2) cnt[i] = 0;
}

__global__ void k_degree2(const int* __restrict__ dst1, const int* __restrict__ dst2,
                          int* cnt, int e, int n) {
    int i = blockIdx.x * blockDim.x + threadIdx.x;
    if (i < 2 * e) {
        int d = (i < e) ? dst1[i] : (dst2[i - e] + n);
        atomicAdd(&cnt[d], 1);
    }
}

__global__ void k_part(const int* __restrict__ cnt, int* part, int n2) {
    __shared__ int red[16];
    int i = blockIdx.x * blockDim.x + threadIdx.x;
    int v = (i < n2) ? cnt[i] : 0;
    int lane = threadIdx.x & 31, wid = threadIdx.x >> 5;
    #pragma unroll
    for (int o = 16; o; o >>= 1) v += __shfl_down_sync(0xffffffffu, v, o);
    if (lane == 0) red[wid] = v;
    __syncthreads();
    if (wid == 0) {
        int s = (lane < (blockDim.x >> 5)) ? red[lane] : 0;
        #pragma unroll
        for (int o = 16; o; o >>= 1) s += __shfl_down_sync(0xffffffffu, s, o);
        if (lane == 0) part[blockIdx.x] = s;
    }
}

__global__ void k_scanpart(int* part, int nb) {
    __shared__ int sh[NPART];
    int tid = threadIdx.x;
    sh[tid] = (tid < nb) ? part[tid] : 0;
    __syncthreads();
    for (int d = 1; d < NPART; d <<= 1) {
        int v = (tid >= d) ? sh[tid - d] : 0;
        __syncthreads();
        sh[tid] += v;
        __syncthreads();
    }
    if (tid < nb) part[tid] = (tid == 0) ? 0 : sh[tid - 1];
}

__global__ void k_off(int* cnt, const int* __restrict__ part, int* off,
                      float* dinv, int n2) {
    __shared__ int wsum[16];
    int i = blockIdx.x * blockDim.x + threadIdx.x;
    int lane = threadIdx.x & 31, wid = threadIdx.x >> 5;
    int nw = blockDim.x >> 5;
    int v = (i < n2) ? cnt[i] : 0;
    int x = v;
    #pragma unroll
    for (int d = 1; d < 32; d <<= 1) {
        int y = __shfl_up_sync(0xffffffffu, x, d);
        if (lane >= d) x += y;
    }
    if (lane == 31) wsum[wid] = x;
    __syncthreads();
    if (wid == 0) {
        int s = (lane < nw) ? wsum[lane] : 0;
        #pragma unroll
        for (int d = 1; d < 32; d <<= 1) {
            int y = __shfl_up_sync(0xffffffffu, s, d);
            if (lane >= d) s += y;
        }
        wsum[lane] = s;
    }
    __syncthreads();
    int excl = x - v + ((wid == 0) ? 0 : wsum[wid - 1]) + part[blockIdx.x];
    if (i < n2) {
        off[i]  = excl;
        dinv[i] = rsqrtf((float)(v + 1));
        cnt[i]  = excl;          // cursor for fill
        if (i == n2 - 1) off[n2] = excl + v;
    }
}

__global__ void k_fill2(const int* __restrict__ src1, const int* __restrict__ dst1,
                        const int* __restrict__ src2, const int* __restrict__ dst2,
                        int* cnt, int* csr, int e, int n) {
    int i = blockIdx.x * blockDim.x + threadIdx.x;
    if (i < 2 * e) {
        int s, d;
        if (i < e) { s = src1[i];     d = dst1[i]; }
        else       { s = src2[i - e] + n; d = dst2[i - e] + n; }
        int pos = atomicAdd(&cnt[d], 1);
        csr[pos] = s;
    }
}

// ---------------- packed-f32x2 GEMM, optional dinv prescale, fp16 out -------
__device__ __forceinline__ void fma_f32x2(unsigned long long& d,
                                          unsigned long long a,
                                          unsigned long long b) {
    asm("fma.rn.f32x2 %0, %1, %2, %0;" : "+l"(d) : "l"(a), "l"(b));
}

__global__ __launch_bounds__(256) void k_gemm_p2(
        const float* __restrict__ A, const float* __restrict__ W,
        const float* __restrict__ dinv, __half* __restrict__ out, int M) {
    extern __shared__ float sm[];
    float2* Ws2 = (float2*)sm;            // [64][128] float2 = 64KB
    float*  As  = sm + 64 * 128 * 2;      // [64][128] float  = 32KB
    int tid = threadIdx.x;

    for (int i = tid; i < 64 * 32; i += 256) {
        int kp = i >> 5, c4 = i & 31;
        float4 w0 = ((const float4*)W)[(2 * kp)     * 32 + c4];
        float4 w1 = ((const float4*)W)[(2 * kp + 1) * 32 + c4];
        float2* dstp = Ws2 + kp * 128 + (c4 << 2);
        dstp[0] = make_float2(w0.x, w1.x);
        dstp[1] = make_float2(w0.y, w1.y);
        dstp[2] = make_float2(w0.z, w1.z);
        dstp[3] = make_float2(w0.w, w1.w);
    }
    int rowbase = blockIdx.x * 64;
    for (int i = tid; i < 64 * 32; i += 256) {
        int r = i >> 5, c4 = i & 31;
        float4 v = make_float4(0.f, 0.f, 0.f, 0.f);
        if (rowbase + r < M) v = ((const float4*)A)[(rowbase + r) * 32 + c4];
        *(float4*)(As + r * 128 + (c4 << 2)) = v;
    }
    __syncthreads();

    int lane = tid & 31, w = tid >> 5;
    unsigned long long acc[8][4];
    #pragma unroll
    for (int r = 0; r < 8; r++)
        #pragma unroll
        for (int j = 0; j < 4; j++) acc[r][j] = 0ull;

    const unsigned long long* Wsu = (const unsigned long long*)Ws2;
    #pragma unroll 4
    for (int kp = 0; kp < 64; kp++) {
        unsigned long long w2[4];
        #pragma unroll
        for (int j = 0; j < 4; j++) w2[j] = Wsu[kp * 128 + lane + 32 * j];
        #pragma unroll
        for (int r = 0; r < 8; r++) {
            unsigned long long a2 =
                *(const unsigned long long*)(As + (w + r * 8) * 128 + 2 * kp);
            #pragma unroll
            for (int j = 0; j < 4; j++) fma_f32x2(acc[r][j], a2, w2[j]);
        }
    }

    #pragma unroll
    for (int r = 0; r < 8; r++) {
        int row = rowbase + w + r * 8;
        if (row < M) {
            float dv = dinv ? dinv[row] : 1.f;
            #pragma unroll
            for (int j = 0; j < 4; j++) {
                unsigned long long u = acc[r][j];
                float lo = __uint_as_float((unsigned int)(u & 0xffffffffu));
                float hi = __uint_as_float((unsigned int)(u >> 32));
                out[row * 128 + lane + 32 * j] = __float2half_rn(dv * (lo + hi));
            }
        }
    }
}
#define GEMM_SMEM ((64 * 128 * 2 + 64 * 128) * sizeof(float))

// ---------------- prescale (layer 1 only): Ph[row] *= dinv[row] -------------
__global__ void k_prescale(uint2* Ph, const float* __restrict__ dinv, int cnt32) {
    int i = blockIdx.x * blockDim.x + threadIdx.x;
    if (i >= cnt32) return;
    int row = i >> 5;
    float dv = dinv[row];
    uint2 u = Ph[i];
    __half2* h = (__half2*)&u;
    float2 f0 = __half22float2(h[0]);
    float2 f1 = __half22float2(h[1]);
    h[0] = __floats2half2_rn(dv * f0.x, dv * f0.y);
    h[1] = __floats2half2_rn(dv * f1.x, dv * f1.y);
    Ph[i] = u;
}

// ---------------- gather: warp per node in [base, base+cnt) -----------------
// All arrays indexed with GLOBAL node ids (csr holds global ids).
__global__ void k_gather(const uint2* __restrict__ P, const float* __restrict__ bias,
                         const float4* __restrict__ Hres, float4* __restrict__ out,
                         const int* __restrict__ off, const int* __restrict__ csr,
                         const float* __restrict__ dinv, int base, int cnt, int mode) {
    int gw = (blockIdx.x * blockDim.x + threadIdx.x) >> 5;
    if (gw >= cnt) return;
    int lane = threadIdx.x & 31;
    int v = base + gw;
    int off0 = off[v], off1 = off[v + 1];
    float dv = dinv[v];
    uint2 bu = P[v * 32 + lane];
    const __half2* bh = (const __half2*)&bu;
    float2 b0 = __half22float2(bh[0]);
    float2 b1 = __half22float2(bh[1]);
    float4 acc = make_float4(b0.x, b0.y, b1.x, b1.y);   // self term P[v]
    for (int j = off0; j < off1; j += 32) {
        int idx = j + lane;
        int u = (idx < off1) ? csr[idx] : 0;
        int m = off1 - j; if (m > 32) m = 32;
        #pragma unroll 4
        for (int i = 0; i < m; i++) {
            int uu = __shfl_sync(0xffffffffu, u, i);
            uint2 hu = P[uu * 32 + lane];
            const __half2* hh = (const __half2*)&hu;
            float2 f0 = __half22float2(hh[0]);
            float2 f1 = __half22float2(hh[1]);
            acc.x += f0.x; acc.y += f0.y;
            acc.z += f1.x; acc.w += f1.y;
        }
    }
    const float4* b4 = (const float4*)bias;
    float4 bb = b4[lane];
    float4 r;
    r.x = fmaxf(fmaf(dv, acc.x, bb.x), 0.f);
    r.y = fmaxf(fmaf(dv, acc.y, bb.y), 0.f);
    r.z = fmaxf(fmaf(dv, acc.z, bb.z), 0.f);
    r.w = fmaxf(fmaf(dv, acc.w, bb.w), 0.f);
    if (mode == 1) {
        float4 h = Hres[v * 32 + lane];
        r.x += h.x; r.y += h.y; r.z += h.z; r.w += h.w;
    }
    out[v * 32 + lane] = r;
}

// ---------------- pooling (one encoder; binary-search bounds) ---------------
__global__ void k_pool(const float4* __restrict__ H, float4* __restrict__ pool,
                       const int* __restrict__ batch, int n, int g, int rowbase) {
    int gw = (blockIdx.x * blockDim.x + threadIdx.x) >> 5;
    if (gw >= g) return;
    int lane = threadIdx.x & 31;
    int lo = 0, hi = n;
    while (lo < hi) { int mid = (lo + hi) >> 1; if (batch[mid] < gw) lo = mid + 1; else hi = mid; }
    int s = lo;
    hi = n;
    while (lo < hi) { int mid = (lo + hi) >> 1; if (batch[mid] < gw + 1) lo = mid + 1; else hi = mid; }
    int e = lo;
    float4 acc = make_float4(0.f, 0.f, 0.f, 0.f);
    for (int r = s; r < e; r++) {
        float4 v = H[(rowbase + r) * 32 + lane];
        acc.x += v.x; acc.y += v.y; acc.z += v.z; acc.w += v.w;
    }
    float sc = (e > s) ? 1.0f / (float)(e - s) : 0.f;
    pool[gw * 32 + lane] = make_float4(acc.x * sc, acc.y * sc, acc.z * sc, acc.w * sc);
}

// ---------------- small GEMM: warp per row (batched M=1024) ----------------
template <int NPER>
__global__ void k_gemm_small(const float* __restrict__ A, const float* __restrict__ W,
                             const float* __restrict__ bias, float* __restrict__ out,
                             int M, int K, int N, int relu) {
    int gw = (blockIdx.x * blockDim.x + threadIdx.x) >> 5;
    if (gw >= M) return;
    int lane = threadIdx.x & 31;
    float acc[NPER];
    #pragma unroll
    for (int j = 0; j < NPER; j++) acc[j] = 0.f;
    const float* a = A + gw * K;
    for (int k = 0; k < K; k++) {
        float av = __ldg(a + k);
        const float* wr = W + k * N;
        #pragma unroll
        for (int j = 0; j < NPER; j++) acc[j] += av * __ldg(wr + lane + 32 * j);
    }
    #pragma unroll
    for (int j = 0; j < NPER; j++) {
        float v = acc[j] + bias[lane + 32 * j];
        if (relu) v = fmaxf(v, 0.f);
        out[gw * N + lane + 32 * j] = v;
    }
}

// ---------------- batchnorm: per-encoder stats, grid = 2*cols ---------------
__global__ void k_bn2(const float* __restrict__ x, const float* __restrict__ gamma,
                      const float* __restrict__ beta, float* __restrict__ out,
                      int rows, int cols, int relu) {
    int col = blockIdx.x % cols;
    int enc = blockIdx.x / cols;
    const float* xe = x + (size_t)enc * rows * cols;
    float* oute = out + (size_t)enc * rows * cols;
    int tid = threadIdx.x, lane = tid & 31, wid = tid >> 5;
    __shared__ float red[8];
    __shared__ float s_m, s_inv;
    float s = 0.f, s2 = 0.f;
    for (int r = tid; r < rows; r += blockDim.x) {
        float v = xe[r * cols + col];
        s += v; s2 += v * v;
    }
    #pragma unroll
    for (int o = 16; o; o >>= 1) {
        s  += __shfl_down_sync(0xffffffffu, s, o);
        s2 += __shfl_down_sync(0xffffffffu, s2, o);
    }
    if (lane == 0) { red[wid] = s; red[4 + wid] = s2; }
    __syncthreads();
    if (tid == 0) {
        float ts = red[0] + red[1] + red[2] + red[3];
        float t2 = red[4] + red[5] + red[6] + red[7];
        float m = ts / rows;
        float var = t2 / rows - m * m;
        s_m = m;
        s_inv = rsqrtf(var + 1e-5f);
    }
    __syncthreads();
    float m = s_m, inv = s_inv, ga = gamma[col], be = beta[col];
    for (int r = tid; r < rows; r += blockDim.x) {
        float v = ga * (xe[r * cols + col] - m) * inv + be;
        if (relu) v = fmaxf(v, 0.f);
        oute[r * cols + col] = v;
    }
}

// ---------------- host orchestration ----------------
extern "C" void kernel_launch(void* const* d_in, const int* in_sizes, int n_in,
                              void* d_out, int out_size) {
    const float* x1  = (const float*)d_in[0];
    const int*   ei1 = (const int*)  d_in[1];
    const int*   bt1 = (const int*)  d_in[2];
    const float* x2  = (const float*)d_in[3];
    const int*   ei2 = (const int*)  d_in[4];
    const int*   bt2 = (const int*)  d_in[5];
    const float* W1  = (const float*)d_in[6];
    const float* b1  = (const float*)d_in[7];
    const float* W2  = (const float*)d_in[8];
    const float* b2  = (const float*)d_in[9];
    const float* W3  = (const float*)d_in[10];
    const float* b3  = (const float*)d_in[11];
    const float* Wp1 = (const float*)d_in[12];
    const float* bp1 = (const float*)d_in[13];
    const float* ga1 = (const float*)d_in[14];
    const float* be1 = (const float*)d_in[15];
    const float* Wp2 = (const float*)d_in[16];
    const float* bp2 = (const float*)d_in[17];
    const float* ga2 = (const float*)d_in[18];
    const float* be2 = (const float*)d_in[19];
    const float* Wq1 = (const float*)d_in[20];
    const float* bq1 = (const float*)d_in[21];
    const float* Wq2 = (const float*)d_in[22];
    const float* bq2 = (const float*)d_in[23];

    int n = in_sizes[0] / INF_;
    int e = in_sizes[1] / 2;
    int g = GG;
    int n2 = 2 * n;

    static bool init = false;
    static cudaStream_t sB, sC;          // sB: encoder-2 pipeline; sC: CSR build
    static cudaEvent_t evFork, evBuild, evEnc2;
    if (!init) {
        cudaStreamCreateWithFlags(&sB, cudaStreamNonBlocking);
        cudaStreamCreateWithFlags(&sC, cudaStreamNonBlocking);
        cudaEventCreateWithFlags(&evFork,  cudaEventDisableTiming);
        cudaEventCreateWithFlags(&evBuild, cudaEventDisableTiming);
        cudaEventCreateWithFlags(&evEnc2,  cudaEventDisableTiming);
        cudaFuncSetAttribute(k_gemm_p2, cudaFuncAttributeMaxDynamicSharedMemorySize,
                             GEMM_SMEM);
        init = true;
    }

    MergedScratch* S;
    cudaGetSymbolAddress((void**)&S, g_s);

    const int* src1 = ei1; const int* dst1 = ei1 + e;
    const int* src2 = ei2; const int* dst2 = ei2 + e;

    float* out = (float*)d_out;
    float* pout = out;                        // p1|p2 contiguous [2g, PROJ]
    float* zout = out + 2 * (size_t)g * PROJ; // z1|z2 contiguous [2g, PROJ]

    int tb = 256;
    int nb512 = (n2 + 511) / 512;             // 196 <= NPART

    // ---- fork ----
    cudaEventRecord(evFork, 0);
    cudaStreamWaitEvent(sB, evFork, 0);
    cudaStreamWaitEvent(sC, evFork, 0);

    // CSR build (merged, once) on sC
    k_zero   <<<(n2 + tb - 1) / tb, tb, 0, sC>>>(S->cnt, n2);
    k_degree2<<<(2 * e + tb - 1) / tb, tb, 0, sC>>>(dst1, dst2, S->cnt, e, n);
    k_part   <<<nb512, 512, 0, sC>>>(S->cnt, S->part, n2);
    k_scanpart<<<1, NPART, 0, sC>>>(S->part, nb512);
    k_off    <<<nb512, 512, 0, sC>>>(S->cnt, S->part, S->off, S->dinv, n2);
    k_fill2  <<<(2 * e + tb - 1) / tb, tb, 0, sC>>>(src1, dst1, src2, dst2,
                                                    S->cnt, S->csr, e, n);
    cudaEventRecord(evBuild, sC);

    // layer-1 GEMMs (no dinv needed) run concurrently with the build
    int gemm_grid1 = (n + 63) / 64;
    __half* Ph1 = S->Ph;
    __half* Ph2 = S->Ph + (size_t)n * HID;
    k_gemm_p2<<<gemm_grid1, 256, GEMM_SMEM, 0>>>(x1, W1, nullptr, Ph1, n);
    k_gemm_p2<<<gemm_grid1, 256, GEMM_SMEM, sB>>>(x2, W1, nullptr, Ph2, n);

    // both pipelines wait for the build
    cudaStreamWaitEvent(0, evBuild, 0);
    cudaStreamWaitEvent(sB, evBuild, 0);

    // ---- per-encoder pipelines (overlap: gemm(fma) ∥ gather(L2)) ----
    int gath_grid = (n * 32 + tb - 1) / tb;
    int pre_grid  = (n * 32 + tb - 1) / tb;
    const uint2* Ph = (const uint2*)S->Ph;
    float4* Ha = (float4*)S->Ha;
    float4* Hb = (float4*)S->Hb;
    float* Ha1f = S->Ha;                    float* Ha2f = S->Ha + (size_t)n * HID;
    float* Hb1f = S->Hb;                    float* Hb2f = S->Hb + (size_t)n * HID;

    // encoder 1 on stream 0
    k_prescale<<<pre_grid, tb, 0, 0>>>((uint2*)Ph1, S->dinv, n * 32);
    k_gather<<<gath_grid, tb, 0, 0>>>(Ph, b1, nullptr, Ha, S->off, S->csr, S->dinv, 0, n, 0);
    k_gemm_p2<<<gemm_grid1, 256, GEMM_SMEM, 0>>>(Ha1f, W2, S->dinv, Ph1, n);
    k_gather<<<gath_grid, tb, 0, 0>>>(Ph, b2, Ha, Hb, S->off, S->csr, S->dinv, 0, n, 1);
    k_gemm_p2<<<gemm_grid1, 256, GEMM_SMEM, 0>>>(Hb1f, W3, S->dinv, Ph1, n);
    k_gather<<<gath_grid, tb, 0, 0>>>(Ph, b3, Hb, Ha, S->off, S->csr, S->dinv, 0, n, 1);
    k_pool<<<(g * 32 + tb - 1) / tb, tb, 0, 0>>>(Ha, (float4*)S->pool, bt1, n, g, 0);

    // encoder 2 on sB (node ids offset by n; dinv/off/csr are global)
    k_prescale<<<pre_grid, tb, 0, sB>>>((uint2*)Ph2, S->dinv + n, n * 32);
    k_gather<<<gath_grid, tb, 0, sB>>>(Ph, b1, nullptr, Ha, S->off, S->csr, S->dinv, n, n, 0);
    k_gemm_p2<<<gemm_grid1, 256, GEMM_SMEM, sB>>>(Ha2f, W2, S->dinv + n, Ph2, n);
    k_gather<<<gath_grid, tb, 0, sB>>>(Ph, b2, Ha, Hb, S->off, S->csr, S->dinv, n, n, 1);
    k_gemm_p2<<<gemm_grid1, 256, GEMM_SMEM, sB>>>(Hb2f, W3, S->dinv + n, Ph2, n);
    k_gather<<<gath_grid, tb, 0, sB>>>(Ph, b3, Hb, Ha, S->off, S->csr, S->dinv, n, n, 1);
    k_pool<<<(g * 32 + tb - 1) / tb, tb, 0, sB>>>(Ha, (float4*)(S->pool + (size_t)g * HID),
                                                  bt2, n, g, n);

    // ---- join, then batched head: M = 2g = 1024, BN per-encoder ----
    cudaEventRecord(evEnc2, sB);
    cudaStreamWaitEvent(0, evEnc2, 0);

    int M2 = 2 * g;
    int gw_blocks = (M2 * 32 + 255) / 256;
    k_gemm_small<8><<<gw_blocks, 256>>>(S->pool, Wp1, bp1, S->t, M2, HID, PROJ, 0);
    k_bn2<<<2 * PROJ, 128>>>(S->t, ga1, be1, S->t, g, PROJ, 1);
    k_gemm_small<8><<<gw_blocks, 256>>>(S->t, Wp2, bp2, S->t2, M2, PROJ, PROJ, 0);
    k_bn2<<<2 * PROJ, 128>>>(S->t2, ga2, be2, zout, g, PROJ, 0);
    k_gemm_small<4><<<gw_blocks, 256>>>(zout, Wq1, bq1, S->q, M2, PROJ, PROJ / 2, 1);
    k_gemm_small<8><<<gw_blocks, 256>>>(S->q, Wq2, bq2, pout, M2, PROJ / 2, PROJ, 0);
}